// round 8
// baseline (speedup 1.0000x reference)
#include <cuda_runtime.h>
#include <cuda_fp16.h>
#include <cstdint>
#include <math.h>

#define NAB 4096
#define NA  2048
#define NN  48
#define FF  128
#define NPAIR (NAB*NN)       // 196608
#define NTILES (NPAIR/128)   // 1536
#define RCUT 5.0f

// A-operand packed strides (bytes/row): ≡64 mod 128 -> conflict-free LDS.128
#define ST1A 320   // K=64:  4 ksteps * 64B + 64 pad
#define ST2A 576   // K=128: 8 ksteps * 64B + 64 pad
// B-operand packed strides: ≡32 mod 128 -> conflict-free LDS.64
#define ST1B 160   // K=64:  4 ksteps * 32B + 32 pad
#define ST2B 288   // K=128: 8 ksteps * 32B + 32 pad

// dynamic smem byte offsets (filter kernel)
#define SM_G   0                      // 128*320  = 40960
#define SM_H   40960                  // 128*576  = 73728
#define SM_B1  114688                 // 128*160  = 20480
#define SM_B2  135168                 // 128*288  = 36864
#define SM_TOT 172032

#define QKV_RPB 27   // qkv rows per filter block (152*27 = 4104 >= 4096)

// Scratch (__device__ globals; no allocations allowed)
__device__ float g_Q[NAB*FF];
__device__ float g_K[NAB*FF];
__device__ float g_V[NAB*FF];

// ---------------------------------------------------------------------------
__device__ __forceinline__ float sspf(float z){
    float az = fabsf(z);
    float e = __expf(-az);
    return fmaxf(z, 0.f) + __logf(1.f + e) - 0.69314718055994531f;
}

// exact fp16 split of a pair: hi word + lo word (a = hi + lo to 2^-22)
__device__ __forceinline__ void split2h(float a, float b, uint32_t &hi, uint32_t &lo){
    __half ah = __float2half(a);
    __half bh = __float2half(b);
    __half al = __float2half(a - __half2float(ah));
    __half bl = __float2half(b - __half2float(bh));
    hi = ((uint32_t)__half_as_ushort(bh) << 16) | (uint32_t)__half_as_ushort(ah);
    lo = ((uint32_t)__half_as_ushort(bl) << 16) | (uint32_t)__half_as_ushort(al);
}
__device__ __forceinline__ uint32_t pack2h(float a, float b){
    return ((uint32_t)__half_as_ushort(__float2half(b)) << 16) |
           (uint32_t)__half_as_ushort(__float2half(a));
}

// A packed addr (pair at even k): granule 16B = {hi(k),hi(k+8),lo(k),lo(k+8)}
__device__ __forceinline__ uint32_t pkA(int row, int k, int st){
    return (uint32_t)(row*st + ((k >> 4) << 6) + (((k & 7) >> 1) << 4) + ((k & 8) >> 1));
}
// B packed addr: unit 8B = {b(k), b(k+8)}
__device__ __forceinline__ uint32_t pkB(int row, int k, int st){
    return (uint32_t)(row*st + ((k >> 4) << 5) + (((k & 7) >> 1) << 3) + ((k & 8) >> 1));
}

__device__ __forceinline__ void mma_f16(float* c, uint32_t a0, uint32_t a1, uint32_t a2, uint32_t a3,
                                        uint32_t b0, uint32_t b1){
    asm volatile(
        "mma.sync.aligned.m16n8k16.row.col.f32.f16.f16.f32 "
        "{%0,%1,%2,%3}, {%4,%5,%6,%7}, {%8,%9}, {%0,%1,%2,%3};"
        : "+f"(c[0]), "+f"(c[1]), "+f"(c[2]), "+f"(c[3])
        : "r"(a0), "r"(a1), "r"(a2), "r"(a3), "r"(b0), "r"(b1));
}

// group barrier (128 threads), named barrier id 1..4
__device__ __forceinline__ void barg(int id){
    asm volatile("bar.sync %0, 128;" :: "r"(id) : "memory");
}

// fp16 2-pass GEMM (A split hi/lo exact, B single): warp tile 32x32
template<int KSTEPS, int STA, int STB>
__device__ __forceinline__ void gemm2p(
    const char* __restrict__ A, const char* __restrict__ Bm,
    int m0, int n0, int lane, float acc[2][4][4])
{
    const int rq = lane >> 2, q = lane & 3;
    #pragma unroll
    for (int ks = 0; ks < KSTEPS; ks++){
        const char* Ab = A + ks*64 + q*16;
        const char* Bb = Bm + ks*32 + q*8;
        uint4 a0[2], a1[2]; uint2 bb[4];
        #pragma unroll
        for (int mf = 0; mf < 2; mf++){
            a0[mf] = *(const uint4*)(Ab + (m0 + mf*16 + rq)*STA);
            a1[mf] = *(const uint4*)(Ab + (m0 + mf*16 + 8 + rq)*STA);
        }
        #pragma unroll
        for (int nf = 0; nf < 4; nf++)
            bb[nf] = *(const uint2*)(Bb + (n0 + nf*8 + rq)*STB);
        #pragma unroll
        for (int mf = 0; mf < 2; mf++)
            #pragma unroll
            for (int nf = 0; nf < 4; nf++){
                mma_f16(acc[mf][nf], a0[mf].x, a1[mf].x, a0[mf].y, a1[mf].y, bb[nf].x, bb[nf].y); // hi
                mma_f16(acc[mf][nf], a0[mf].z, a1[mf].z, a0[mf].w, a1[mf].w, bb[nf].x, bb[nf].y); // lo
            }
    }
}

// ---------------------------------------------------------------------------
// Persistent fused QKV-prologue + filter network (fp16x2 HMMA), 512 threads
// ---------------------------------------------------------------------------
__global__ void __launch_bounds__(512,1) filter_kernel(
    const float* __restrict__ f_ij, const float* __restrict__ r_ij,
    const float* __restrict__ Wf1, const float* __restrict__ bf1,
    const float* __restrict__ Wf2, const float* __restrict__ bf2,
    const float* __restrict__ x,
    const float* __restrict__ Wq, const float* __restrict__ Wk,
    const float* __restrict__ Wv,
    float* __restrict__ outW)
{
    extern __shared__ __align__(128) char dynsm[];
    __shared__ float s_cw[128], s_bf1[128], s_bf2[128];

    char* G  = dynsm + SM_G;
    char* H  = dynsm + SM_H;
    char* B1 = dynsm + SM_B1;
    char* B2 = dynsm + SM_B2;

    const int tid  = threadIdx.x;
    const int lane = tid & 31, wid = tid >> 5;
    const int m0 = (wid & 3) * 32;
    const int n0 = (wid >> 2) * 32;
    const int rq = lane >> 2, q = lane & 3;

    // ==== prologue: QKV for this block's row slice (fp32 FFMA) ====
    {
        float* xs = (float*)dynsm;   // [27][128] = 13.8 KB, overlaps G (rewritten later)
        const int r0 = blockIdx.x * QKV_RPB;
        const int nrows = (r0 + QKV_RPB <= NAB) ? QKV_RPB : (NAB - r0);
        for (int i = tid; i < nrows*FF; i += 512) xs[i] = x[(size_t)r0*FF + i];
        __syncthreads();
        const int g = tid >> 7, c = tid & 127;
        for (int rr = g; rr < nrows; rr += 4){
            const float* xr = xs + rr*FF;
            float aq = 0.f, ak = 0.f, av = 0.f;
            #pragma unroll 8
            for (int k = 0; k < FF; k++){
                float xv = xr[k];
                aq = fmaf(xv, Wq[k*FF + c], aq);
                ak = fmaf(xv, Wk[k*FF + c], ak);
                av = fmaf(xv, Wv[k*FF + c], av);
            }
            size_t o = (size_t)(r0 + rr)*FF + c;
            g_Q[o] = aq; g_K[o] = ak; g_V[o] = av;
        }
        __syncthreads();
    }

    // ==== weight prep (once per persistent block): transpose + pack fp16 ====
    for (int i = tid; i < 128*32; i += 512){
        int n = i >> 5, p = i & 31, k = p*2;
        float v0 = (k   < 50) ? Wf1[k*FF + n]     : 0.f;
        float v1 = (k+1 < 50) ? Wf1[(k+1)*FF + n] : 0.f;
        *(uint32_t*)(B1 + pkB(n, k, ST1B)) = pack2h(v0, v1);
    }
    for (int i = tid; i < 128*64; i += 512){
        int n = i >> 6, p = i & 63, k = p*2;
        *(uint32_t*)(B2 + pkB(n, k, ST2B)) = pack2h(Wf2[k*FF + n], Wf2[(k+1)*FF + n]);
    }
    if (tid < 128){ s_bf1[tid] = bf1[tid]; s_bf2[tid] = bf2[tid]; }
    __syncthreads();

    for (int t = blockIdx.x; t < NTILES; t += gridDim.x){
        const int tb = t * 128;

        // ---- load A1 tile: G = 2*f_ij - 1, exact fp16 split ----
        for (int i = tid; i < 128*32; i += 512){
            int row = i >> 5, p = i & 31, k = p*2;
            const float* fp = f_ij + (size_t)(tb + row)*50;
            float g0 = (k   < 50) ? 2.f*fp[k]   - 1.f : 0.f;
            float g1 = (k+1 < 50) ? 2.f*fp[k+1] - 1.f : 0.f;
            uint32_t hi, lo; split2h(g0, g1, hi, lo);
            uint32_t a = pkA(row, k, ST1A);
            *(uint32_t*)(G + a)     = hi;
            *(uint32_t*)(G + a + 8) = lo;
        }
        if (tid < 128){
            float r = r_ij[tb + tid];
            s_cw[tid] = (r < RCUT) ? 0.5f*(__cosf(0.62831853071795865f*r) + 1.f) : 0.f;
        }
        __syncthreads();   // S1

        float rcw0 = s_cw[m0 + rq],      rcw1 = s_cw[m0 + rq + 8];
        float rcw2 = s_cw[m0 + 16 + rq], rcw3 = s_cw[m0 + 16 + rq + 8];

        // ---- GEMM1: D1 = G @ Wf1 ----
        float acc[2][4][4];
        #pragma unroll
        for (int mf=0;mf<2;mf++)
            #pragma unroll
            for (int nf=0;nf<4;nf++)
                #pragma unroll
                for (int u=0;u<4;u++) acc[mf][nf][u] = 0.f;
        gemm2p<4, ST1A, ST1B>(G, B1, m0, n0, lane, acc);

        // ---- epilogue 1: H = ssp(D1 + bf1) -> fp16-split packed into H ----
        #pragma unroll
        for (int mf = 0; mf < 2; mf++){
            const int r = m0 + mf*16 + rq;
            #pragma unroll
            for (int nfp = 0; nfp < 4; nfp += 2){
                int ccA = n0 + nfp*8 + 2*q;
                int ccB = ccA + 8;
                float b0 = s_bf1[ccA], b1 = s_bf1[ccA+1];
                float b2 = s_bf1[ccB], b3 = s_bf1[ccB+1];
                uint32_t h0,l0,h1,l1;
                uint32_t ad = (uint32_t)(r*ST2A + ((n0 + nfp*8) >> 4)*64 + q*16);
                split2h(sspf(acc[mf][nfp][0]+b0),   sspf(acc[mf][nfp][1]+b1),   h0, l0);
                split2h(sspf(acc[mf][nfp+1][0]+b2), sspf(acc[mf][nfp+1][1]+b3), h1, l1);
                *(uint4*)(H + ad) = make_uint4(h0, h1, l0, l1);
                split2h(sspf(acc[mf][nfp][2]+b0),   sspf(acc[mf][nfp][3]+b1),   h0, l0);
                split2h(sspf(acc[mf][nfp+1][2]+b2), sspf(acc[mf][nfp+1][3]+b3), h1, l1);
                *(uint4*)(H + ad + 8*ST2A) = make_uint4(h0, h1, l0, l1);
            }
        }
        __syncthreads();   // S2

        // ---- GEMM2: D2 = H @ Wf2 ----
        #pragma unroll
        for (int mf=0;mf<2;mf++)
            #pragma unroll
            for (int nf=0;nf<4;nf++)
                #pragma unroll
                for (int u=0;u<4;u++) acc[mf][nf][u] = 0.f;
        gemm2p<8, ST2A, ST2B>(H, B2, m0, n0, lane, acc);

        // ---- epilogue 2: W = (D2 + bf2) * cutoff, direct global store ----
        #pragma unroll
        for (int mf = 0; mf < 2; mf++){
            int rr = m0 + mf*16 + rq;
            float cw0 = mf ? rcw2 : rcw0;
            float cw1 = mf ? rcw3 : rcw1;
            #pragma unroll
            for (int nf = 0; nf < 4; nf++){
                int cc = n0 + nf*8 + 2*q;
                float b0 = s_bf2[cc], b1 = s_bf2[cc+1];
                float2 o0, o1;
                o0.x = (acc[mf][nf][0] + b0) * cw0;
                o0.y = (acc[mf][nf][1] + b1) * cw0;
                o1.x = (acc[mf][nf][2] + b0) * cw1;
                o1.y = (acc[mf][nf][3] + b1) * cw1;
                *(float2*)&outW[((size_t)(tb + rr))*FF + cc]     = o0;
                *(float2*)&outW[((size_t)(tb + rr + 8))*FF + cc] = o1;
            }
        }
        // next-iteration S1 protects G/s_cw rewrites
    }
}

// ---------------------------------------------------------------------------
// Persistent attention + output projection: Wo staged in smem once per block,
// 4 atom-groups x 128 threads, group-scoped named barriers
// ---------------------------------------------------------------------------
__global__ void __launch_bounds__(512,1) attn_out_kernel(
    const int* __restrict__ neighbors, const int* __restrict__ pmask,
    const float* __restrict__ W,
    const float* __restrict__ Wo, const float* __restrict__ bo,
    float* __restrict__ outM)
{
    extern __shared__ float sWo[];     // [128][128] = 64 KB
    __shared__ float s_q[4][128], s_m[4][128];
    __shared__ float s_sc[4][64], s_at[4][64];
    __shared__ int   s_nb[4][48], s_mk[4][48];

    const int tid = threadIdx.x;
    const int grp = tid >> 7, lt = tid & 127;
    const int lane = tid & 31, wd = (tid >> 5) & 3;
    const int bid = grp + 1;           // named barrier id per group

    for (int i = tid*4; i < FF*FF; i += 2048)
        *(float4*)&sWo[i] = *(const float4*)&Wo[i];
    __syncthreads();

    float bov = bo[lt];

    for (int it = 0; it < 7; it++){
        const int atom = it*608 + blockIdx.x*4 + grp;
        if (atom < NAB){
            s_q[grp][lt] = g_Q[(size_t)atom*FF + lt];
            if (lt < NN){
                s_nb[grp][lt] = neighbors[atom*NN + lt] + (atom >> 11)*NA;
                s_mk[grp][lt] = pmask[atom*NN + lt];
            }
            barg(bid);

            for (int j = wd; j < 49; j += 4){
                int row = j ? s_nb[grp][j-1] : atom;
                float4 kv = *(const float4*)&g_K[(size_t)row*FF + lane*4];
                float4 qv = *(const float4*)&s_q[grp][lane*4];
                float d = kv.x*qv.x + kv.y*qv.y + kv.z*qv.z + kv.w*qv.w;
                #pragma unroll
                for (int o=16;o;o>>=1) d += __shfl_xor_sync(0xffffffffu, d, o);
                if (lane == 0){
                    float s = d * 0.08838834764831845f;   // 1/sqrt(128)
                    if (j > 0 && s_mk[grp][j-1] == 0) s = -1e9f;
                    s_sc[grp][j] = s;
                }
            }
            barg(bid);

            if (wd == 0){
                float v0 = (lane      < 49) ? s_sc[grp][lane]      : -3.4e38f;
                float v1 = (lane + 32 < 49) ? s_sc[grp][lane + 32] : -3.4e38f;
                float mx = fmaxf(v0, v1);
                #pragma unroll
                for (int o=16;o;o>>=1) mx = fmaxf(mx, __shfl_xor_sync(0xffffffffu, mx, o));
                float e0 = (lane      < 49) ? __expf(v0 - mx) : 0.f;
                float e1 = (lane + 32 < 49) ? __expf(v1 - mx) : 0.f;
                float s = e0 + e1;
                #pragma unroll
                for (int o=16;o;o>>=1) s += __shfl_xor_sync(0xffffffffu, s, o);
                float inv = 1.f / s;
                if (lane      < 49) s_at[grp][lane]      = e0 * inv;
                if (lane + 32 < 49) s_at[grp][lane + 32] = e1 * inv;
            }
            barg(bid);

            float acc = s_at[grp][0] * g_V[(size_t)atom*FF + lt];
            const float* wrow = W + (size_t)atom*NN*FF + lt;
            #pragma unroll 4
            for (int j = 0; j < NN; j++)
                acc += s_at[grp][j+1] * g_V[(size_t)s_nb[grp][j]*FF + lt] * wrow[(size_t)j*FF];
            s_m[grp][lt] = acc;
            barg(bid);

            // out = ssp(m @ Wo + bo) from smem Wo
            float o0 = 0.f, o1 = 0.f;
            #pragma unroll 16
            for (int k = 0; k < FF; k += 2){
                o0 = fmaf(s_m[grp][k],   sWo[k*FF + lt],     o0);
                o1 = fmaf(s_m[grp][k+1], sWo[(k+1)*FF + lt], o1);
            }
            outM[(size_t)atom*FF + lt] = sspf(o0 + o1 + bov);
            barg(bid);   // protect group smem before next iteration
        }
    }
}

// ---------------------------------------------------------------------------
extern "C" void kernel_launch(void* const* d_in, const int* in_sizes, int n_in,
                              void* d_out, int out_size)
{
    // order: e,x,t,r_ij,neighbors,pairwise_mask,f_ij,Wf1,bf1,Wf2,bf2,Wq,Wk,Wv,Wo,bo
    const float* x         = (const float*)d_in[1];
    const float* r_ij      = (const float*)d_in[3];
    const int*   neighbors = (const int*)  d_in[4];
    const int*   pmask     = (const int*)  d_in[5];
    const float* f_ij      = (const float*)d_in[6];
    const float* Wf1       = (const float*)d_in[7];
    const float* bf1       = (const float*)d_in[8];
    const float* Wf2       = (const float*)d_in[9];
    const float* bf2       = (const float*)d_in[10];
    const float* Wq        = (const float*)d_in[11];
    const float* Wk        = (const float*)d_in[12];
    const float* Wv        = (const float*)d_in[13];
    const float* Wo        = (const float*)d_in[14];
    const float* bo        = (const float*)d_in[15];

    float* out  = (float*)d_out;
    float* outM = out;                        // m: [B,Na,F]
    float* outW = out + (size_t)NAB * FF;     // W: [B,Na,Nn,F]

    size_t smF = SM_TOT;                      // 168 KB
    size_t smA = (size_t)FF*FF*sizeof(float); // 64 KB

    cudaFuncSetAttribute(filter_kernel,   cudaFuncAttributeMaxDynamicSharedMemorySize, (int)smF);
    cudaFuncSetAttribute(attn_out_kernel, cudaFuncAttributeMaxDynamicSharedMemorySize, (int)smA);

    filter_kernel<<<152, 512, smF>>>(f_ij, r_ij, Wf1, bf1, Wf2, bf2,
                                     x, Wq, Wk, Wv, outW);
    attn_out_kernel<<<152, 512, smA>>>(neighbors, pmask, outW, Wo, bo, outM);
}

// round 10
// speedup vs baseline: 1.0338x; 1.0338x over previous
#include <cuda_runtime.h>
#include <cuda_fp16.h>
#include <cstdint>
#include <math.h>

#define NAB 4096
#define NA  2048
#define NN  48
#define FF  128
#define NPAIR (NAB*NN)       // 196608
#define NTILES (NPAIR/128)   // 1536
#define RCUT 5.0f

// A-operand packed strides (bytes/row): ≡64 mod 128 -> conflict-free LDS.128
#define ST1A 320   // K=64:  4 ksteps * 64B + 64 pad
#define ST2A 576   // K=128: 8 ksteps * 64B + 64 pad
// B-operand packed strides: ≡32 mod 128 -> conflict-free LDS.64
#define ST1B 160   // K=64:  4 ksteps * 32B + 32 pad
#define ST2B 288   // K=128: 8 ksteps * 32B + 32 pad

// dynamic smem byte offsets (filter kernel)
#define SM_G   0                      // 128*320  = 40960
#define SM_H   40960                  // 128*576  = 73728
#define SM_B1  114688                 // 128*160  = 20480
#define SM_B2  135168                 // 128*288  = 36864
#define SM_TOT 172032

// Scratch (__device__ globals; no allocations allowed)
__device__ float g_Q[NAB*FF];
__device__ float g_K[NAB*FF];
__device__ float g_V[NAB*FF];

// ---------------------------------------------------------------------------
__device__ __forceinline__ float sspf(float z){
    float az = fabsf(z);
    float e = __expf(-az);
    return fmaxf(z, 0.f) + __logf(1.f + e) - 0.69314718055994531f;
}

// exact fp16 split of a pair: hi word + lo word (a = hi + lo to 2^-22)
__device__ __forceinline__ void split2h(float a, float b, uint32_t &hi, uint32_t &lo){
    __half ah = __float2half(a);
    __half bh = __float2half(b);
    __half al = __float2half(a - __half2float(ah));
    __half bl = __float2half(b - __half2float(bh));
    hi = ((uint32_t)__half_as_ushort(bh) << 16) | (uint32_t)__half_as_ushort(ah);
    lo = ((uint32_t)__half_as_ushort(bl) << 16) | (uint32_t)__half_as_ushort(al);
}
__device__ __forceinline__ uint32_t pack2h(float a, float b){
    return ((uint32_t)__half_as_ushort(__float2half(b)) << 16) |
           (uint32_t)__half_as_ushort(__float2half(a));
}

// A packed addr (pair at even k): granule 16B = {hi(k),hi(k+8),lo(k),lo(k+8)}
__device__ __forceinline__ uint32_t pkA(int row, int k, int st){
    return (uint32_t)(row*st + ((k >> 4) << 6) + (((k & 7) >> 1) << 4) + ((k & 8) >> 1));
}
// B packed addr: unit 8B = {b(k), b(k+8)}
__device__ __forceinline__ uint32_t pkB(int row, int k, int st){
    return (uint32_t)(row*st + ((k >> 4) << 5) + (((k & 7) >> 1) << 3) + ((k & 8) >> 1));
}

__device__ __forceinline__ void mma_f16(float* c, uint32_t a0, uint32_t a1, uint32_t a2, uint32_t a3,
                                        uint32_t b0, uint32_t b1){
    asm volatile(
        "mma.sync.aligned.m16n8k16.row.col.f32.f16.f16.f32 "
        "{%0,%1,%2,%3}, {%4,%5,%6,%7}, {%8,%9}, {%0,%1,%2,%3};"
        : "+f"(c[0]), "+f"(c[1]), "+f"(c[2]), "+f"(c[3])
        : "r"(a0), "r"(a1), "r"(a2), "r"(a3), "r"(b0), "r"(b1));
}

// group barrier (128 threads), named barrier ids 1..2
__device__ __forceinline__ void barg(int id){
    asm volatile("bar.sync %0, 128;" :: "r"(id) : "memory");
}

// fp16 2-pass GEMM (A split hi/lo exact, B single): warp tile 32x32
template<int KSTEPS, int STA, int STB>
__device__ __forceinline__ void gemm2p(
    const char* __restrict__ A, const char* __restrict__ Bm,
    int m0, int n0, int lane, float acc[2][4][4])
{
    const int rq = lane >> 2, q = lane & 3;
    #pragma unroll
    for (int ks = 0; ks < KSTEPS; ks++){
        const char* Ab = A + ks*64 + q*16;
        const char* Bb = Bm + ks*32 + q*8;
        uint4 a0[2], a1[2]; uint2 bb[4];
        #pragma unroll
        for (int mf = 0; mf < 2; mf++){
            a0[mf] = *(const uint4*)(Ab + (m0 + mf*16 + rq)*STA);
            a1[mf] = *(const uint4*)(Ab + (m0 + mf*16 + 8 + rq)*STA);
        }
        #pragma unroll
        for (int nf = 0; nf < 4; nf++)
            bb[nf] = *(const uint2*)(Bb + (n0 + nf*8 + rq)*STB);
        #pragma unroll
        for (int mf = 0; mf < 2; mf++)
            #pragma unroll
            for (int nf = 0; nf < 4; nf++){
                mma_f16(acc[mf][nf], a0[mf].x, a1[mf].x, a0[mf].y, a1[mf].y, bb[nf].x, bb[nf].y); // hi
                mma_f16(acc[mf][nf], a0[mf].z, a1[mf].z, a0[mf].w, a1[mf].w, bb[nf].x, bb[nf].y); // lo
            }
    }
}

// ---------------------------------------------------------------------------
// Persistent fused filter network (fp16x2 HMMA), 512 threads / 16 warps
// ---------------------------------------------------------------------------
__global__ void __launch_bounds__(512,1) filter_kernel(
    const float* __restrict__ f_ij, const float* __restrict__ r_ij,
    const float* __restrict__ Wf1, const float* __restrict__ bf1,
    const float* __restrict__ Wf2, const float* __restrict__ bf2,
    float* __restrict__ outW)
{
    extern __shared__ __align__(128) char dynsm[];
    __shared__ float s_cw[128], s_bf1[128], s_bf2[128];

    char* G  = dynsm + SM_G;
    char* H  = dynsm + SM_H;
    char* B1 = dynsm + SM_B1;
    char* B2 = dynsm + SM_B2;

    const int tid  = threadIdx.x;
    const int lane = tid & 31, wid = tid >> 5;
    const int m0 = (wid & 3) * 32;
    const int n0 = (wid >> 2) * 32;
    const int rq = lane >> 2, q = lane & 3;

    // ---- weight prep (once per persistent block): transpose + pack fp16 ----
    for (int i = tid; i < 128*32; i += 512){
        int n = i >> 5, p = i & 31, k = p*2;
        float v0 = (k   < 50) ? Wf1[k*FF + n]     : 0.f;
        float v1 = (k+1 < 50) ? Wf1[(k+1)*FF + n] : 0.f;
        *(uint32_t*)(B1 + pkB(n, k, ST1B)) = pack2h(v0, v1);
    }
    for (int i = tid; i < 128*64; i += 512){
        int n = i >> 6, p = i & 63, k = p*2;
        *(uint32_t*)(B2 + pkB(n, k, ST2B)) = pack2h(Wf2[k*FF + n], Wf2[(k+1)*FF + n]);
    }
    if (tid < 128){ s_bf1[tid] = bf1[tid]; s_bf2[tid] = bf2[tid]; }
    __syncthreads();

    for (int t = blockIdx.x; t < NTILES; t += gridDim.x){
        const int tb = t * 128;

        // ---- load A1 tile: G = 2*f_ij - 1, exact fp16 split ----
        for (int i = tid; i < 128*32; i += 512){
            int row = i >> 5, p = i & 31, k = p*2;
            const float* fp = f_ij + (size_t)(tb + row)*50;
            float g0 = (k   < 50) ? 2.f*fp[k]   - 1.f : 0.f;
            float g1 = (k+1 < 50) ? 2.f*fp[k+1] - 1.f : 0.f;
            uint32_t hi, lo; split2h(g0, g1, hi, lo);
            uint32_t a = pkA(row, k, ST1A);
            *(uint32_t*)(G + a)     = hi;
            *(uint32_t*)(G + a + 8) = lo;
        }
        if (tid < 128){
            float r = r_ij[tb + tid];
            s_cw[tid] = (r < RCUT) ? 0.5f*(__cosf(0.62831853071795865f*r) + 1.f) : 0.f;
        }
        __syncthreads();   // S1

        // cutoff weights for this warp's rows -> regs (safe: before S2)
        float rcw0 = s_cw[m0 + rq],      rcw1 = s_cw[m0 + rq + 8];
        float rcw2 = s_cw[m0 + 16 + rq], rcw3 = s_cw[m0 + 16 + rq + 8];

        // ---- GEMM1: D1 = G @ Wf1 ----
        float acc[2][4][4];
        #pragma unroll
        for (int mf=0;mf<2;mf++)
            #pragma unroll
            for (int nf=0;nf<4;nf++)
                #pragma unroll
                for (int u=0;u<4;u++) acc[mf][nf][u] = 0.f;
        gemm2p<4, ST1A, ST1B>(G, B1, m0, n0, lane, acc);

        // ---- epilogue 1: H = ssp(D1 + bf1) -> fp16-split packed into H ----
        #pragma unroll
        for (int mf = 0; mf < 2; mf++){
            const int r = m0 + mf*16 + rq;
            #pragma unroll
            for (int nfp = 0; nfp < 4; nfp += 2){
                int ccA = n0 + nfp*8 + 2*q;
                int ccB = ccA + 8;
                float b0 = s_bf1[ccA], b1 = s_bf1[ccA+1];
                float b2 = s_bf1[ccB], b3 = s_bf1[ccB+1];
                uint32_t h0,l0,h1,l1;
                uint32_t ad = (uint32_t)(r*ST2A + ((n0 + nfp*8) >> 4)*64 + q*16);
                split2h(sspf(acc[mf][nfp][0]+b0),   sspf(acc[mf][nfp][1]+b1),   h0, l0);
                split2h(sspf(acc[mf][nfp+1][0]+b2), sspf(acc[mf][nfp+1][1]+b3), h1, l1);
                *(uint4*)(H + ad) = make_uint4(h0, h1, l0, l1);
                split2h(sspf(acc[mf][nfp][2]+b0),   sspf(acc[mf][nfp][3]+b1),   h0, l0);
                split2h(sspf(acc[mf][nfp+1][2]+b2), sspf(acc[mf][nfp+1][3]+b3), h1, l1);
                *(uint4*)(H + ad + 8*ST2A) = make_uint4(h0, h1, l0, l1);
            }
        }
        __syncthreads();   // S2

        // ---- GEMM2: D2 = H @ Wf2 ----
        #pragma unroll
        for (int mf=0;mf<2;mf++)
            #pragma unroll
            for (int nf=0;nf<4;nf++)
                #pragma unroll
                for (int u=0;u<4;u++) acc[mf][nf][u] = 0.f;
        gemm2p<8, ST2A, ST2B>(H, B2, m0, n0, lane, acc);

        // ---- epilogue 2: W = (D2 + bf2) * cutoff, direct global store ----
        #pragma unroll
        for (int mf = 0; mf < 2; mf++){
            int rr = m0 + mf*16 + rq;
            float cw0 = mf ? rcw2 : rcw0;
            float cw1 = mf ? rcw3 : rcw1;
            #pragma unroll
            for (int nf = 0; nf < 4; nf++){
                int cc = n0 + nf*8 + 2*q;
                float b0 = s_bf2[cc], b1 = s_bf2[cc+1];
                float2 o0, o1;
                o0.x = (acc[mf][nf][0] + b0) * cw0;
                o0.y = (acc[mf][nf][1] + b1) * cw0;
                o1.x = (acc[mf][nf][2] + b0) * cw1;
                o1.y = (acc[mf][nf][3] + b1) * cw1;
                *(float2*)&outW[((size_t)(tb + rr))*FF + cc]     = o0;
                *(float2*)&outW[((size_t)(tb + rr + 8))*FF + cc] = o1;
            }
        }
        // next-iteration S1 protects G/s_cw rewrites (H reads finished before S1)
    }
}

// ---------------------------------------------------------------------------
// QKV: x @ {Wq,Wk,Wv}, 32-row x 64-col blocks (gridDim.y = 6)
// ---------------------------------------------------------------------------
__global__ void __launch_bounds__(256) qkv_kernel(
    const float* __restrict__ x,
    const float* __restrict__ Wq, const float* __restrict__ Wk, const float* __restrict__ Wv)
{
    extern __shared__ char dynsm[];
    float* sW = (float*)dynsm;          // [128][64]
    float* sX = sW + FF*64;             // [32][128]
    const int mat  = blockIdx.y >> 1;
    const int half = blockIdx.y & 1;
    const float* Wsrc = (mat == 0) ? Wq : (mat == 1 ? Wk : Wv);
    float* outp = (mat == 0) ? g_Q : (mat == 1 ? g_K : g_V);
    const int tid = threadIdx.x;
    const int row0 = blockIdx.x * 32;

    for (int i = tid; i < FF*32; i += 256){
        int k = i >> 5, c2 = (i & 31)*2;
        *(float2*)&sW[k*64 + c2] = *(const float2*)&Wsrc[k*FF + half*64 + c2];
    }
    for (int i = tid*4; i < 32*FF; i += 1024)
        *(float4*)&sX[i] = *(const float4*)&x[(size_t)row0*FF + i];
    __syncthreads();

    const int lane = tid & 31, wd = tid >> 5;
    const int c0 = lane * 2;
    float acc[4][2];
    #pragma unroll
    for (int m=0;m<4;m++){ acc[m][0]=0.f; acc[m][1]=0.f; }

    for (int k = 0; k < FF; k += 4){
        float2 bf[4];
        #pragma unroll
        for (int kk=0;kk<4;kk++) bf[kk] = *(float2*)&sW[(k+kk)*64 + c0];
        #pragma unroll
        for (int m=0;m<4;m++){
            float4 av = *(float4*)&sX[(wd*4+m)*FF + k];
            acc[m][0] = fmaf(av.x, bf[0].x, acc[m][0]); acc[m][1] = fmaf(av.x, bf[0].y, acc[m][1]);
            acc[m][0] = fmaf(av.y, bf[1].x, acc[m][0]); acc[m][1] = fmaf(av.y, bf[1].y, acc[m][1]);
            acc[m][0] = fmaf(av.z, bf[2].x, acc[m][0]); acc[m][1] = fmaf(av.z, bf[2].y, acc[m][1]);
            acc[m][0] = fmaf(av.w, bf[3].x, acc[m][0]); acc[m][1] = fmaf(av.w, bf[3].y, acc[m][1]);
        }
    }
    #pragma unroll
    for (int m=0;m<4;m++){
        int r = row0 + wd*4 + m;
        *(float2*)&outp[(size_t)r*FF + half*64 + c0] = make_float2(acc[m][0], acc[m][1]);
    }
}

// ---------------------------------------------------------------------------
// Attention + output projection: 512 blocks x 256 threads, 8 atoms/block
// (two 128-thread groups, 4 pair-iterations), Wo staged in smem per block
// ---------------------------------------------------------------------------
__global__ void __launch_bounds__(256,3) attn_out_kernel(
    const int* __restrict__ neighbors, const int* __restrict__ pmask,
    const float* __restrict__ W,
    const float* __restrict__ Wo, const float* __restrict__ bo,
    float* __restrict__ outM)
{
    extern __shared__ float sWo[];     // [128][128] = 64 KB
    __shared__ float s_q[2][128], s_m[2][128];
    __shared__ float s_sc[2][64], s_at[2][64];
    __shared__ int   s_nb[2][48], s_mk[2][48];

    const int tid = threadIdx.x;
    const int grp = tid >> 7, lt = tid & 127;
    const int lane = tid & 31, wd = (tid >> 5) & 3;
    const int bid = grp + 1;

    for (int i = tid*4; i < FF*FF; i += 1024)
        *(float4*)&sWo[i] = *(const float4*)&Wo[i];
    __syncthreads();

    const float bov = bo[lt];
    const int abase = blockIdx.x * 8 + grp;

    #pragma unroll 1
    for (int it = 0; it < 4; it++){
        const int atom = abase + it*2;

        s_q[grp][lt] = g_Q[(size_t)atom*FF + lt];
        if (lt < NN){
            s_nb[grp][lt] = neighbors[atom*NN + lt] + (atom >> 11)*NA;
            s_mk[grp][lt] = pmask[atom*NN + lt];
        }
        barg(bid);

        for (int j = wd; j < 49; j += 4){
            int row = j ? s_nb[grp][j-1] : atom;
            float4 kv = *(const float4*)&g_K[(size_t)row*FF + lane*4];
            float4 qv = *(const float4*)&s_q[grp][lane*4];
            float d = kv.x*qv.x + kv.y*qv.y + kv.z*qv.z + kv.w*qv.w;
            #pragma unroll
            for (int o=16;o;o>>=1) d += __shfl_xor_sync(0xffffffffu, d, o);
            if (lane == 0){
                float s = d * 0.08838834764831845f;   // 1/sqrt(128)
                if (j > 0 && s_mk[grp][j-1] == 0) s = -1e9f;
                s_sc[grp][j] = s;
            }
        }
        barg(bid);

        if (wd == 0){
            float v0 = (lane      < 49) ? s_sc[grp][lane]      : -3.4e38f;
            float v1 = (lane + 32 < 49) ? s_sc[grp][lane + 32] : -3.4e38f;
            float mx = fmaxf(v0, v1);
            #pragma unroll
            for (int o=16;o;o>>=1) mx = fmaxf(mx, __shfl_xor_sync(0xffffffffu, mx, o));
            float e0 = (lane      < 49) ? __expf(v0 - mx) : 0.f;
            float e1 = (lane + 32 < 49) ? __expf(v1 - mx) : 0.f;
            float s = e0 + e1;
            #pragma unroll
            for (int o=16;o;o>>=1) s += __shfl_xor_sync(0xffffffffu, s, o);
            float inv = 1.f / s;
            if (lane      < 49) s_at[grp][lane]      = e0 * inv;
            if (lane + 32 < 49) s_at[grp][lane + 32] = e1 * inv;
        }
        barg(bid);

        float acc = s_at[grp][0] * g_V[(size_t)atom*FF + lt];
        const float* wrow = W + (size_t)atom*NN*FF + lt;
        #pragma unroll 4
        for (int j = 0; j < NN; j++)
            acc += s_at[grp][j+1] * g_V[(size_t)s_nb[grp][j]*FF + lt] * wrow[(size_t)j*FF];
        s_m[grp][lt] = acc;
        barg(bid);

        // out = ssp(m @ Wo + bo) from smem Wo
        float o0 = 0.f, o1 = 0.f;
        #pragma unroll 16
        for (int k = 0; k < FF; k += 2){
            o0 = fmaf(s_m[grp][k],   sWo[k*FF + lt],     o0);
            o1 = fmaf(s_m[grp][k+1], sWo[(k+1)*FF + lt], o1);
        }
        outM[(size_t)atom*FF + lt] = sspf(o0 + o1 + bov);
        barg(bid);   // protect group smem before next iteration
    }
}

// ---------------------------------------------------------------------------
extern "C" void kernel_launch(void* const* d_in, const int* in_sizes, int n_in,
                              void* d_out, int out_size)
{
    // order: e,x,t,r_ij,neighbors,pairwise_mask,f_ij,Wf1,bf1,Wf2,bf2,Wq,Wk,Wv,Wo,bo
    const float* x         = (const float*)d_in[1];
    const float* r_ij      = (const float*)d_in[3];
    const int*   neighbors = (const int*)  d_in[4];
    const int*   pmask     = (const int*)  d_in[5];
    const float* f_ij      = (const float*)d_in[6];
    const float* Wf1       = (const float*)d_in[7];
    const float* bf1       = (const float*)d_in[8];
    const float* Wf2       = (const float*)d_in[9];
    const float* bf2       = (const float*)d_in[10];
    const float* Wq        = (const float*)d_in[11];
    const float* Wk        = (const float*)d_in[12];
    const float* Wv        = (const float*)d_in[13];
    const float* Wo        = (const float*)d_in[14];
    const float* bo        = (const float*)d_in[15];

    float* out  = (float*)d_out;
    float* outM = out;                        // m: [B,Na,F]
    float* outW = out + (size_t)NAB * FF;     // W: [B,Na,Nn,F]

    size_t smG = (size_t)(FF*64 + 32*FF) * sizeof(float);   // 48 KB
    size_t smF = SM_TOT;                                    // 168 KB
    size_t smA = (size_t)FF*FF*sizeof(float);               // 64 KB

    cudaFuncSetAttribute(qkv_kernel,      cudaFuncAttributeMaxDynamicSharedMemorySize, (int)smG);
    cudaFuncSetAttribute(filter_kernel,   cudaFuncAttributeMaxDynamicSharedMemorySize, (int)smF);
    cudaFuncSetAttribute(attn_out_kernel, cudaFuncAttributeMaxDynamicSharedMemorySize, (int)smA);

    qkv_kernel<<<dim3(NAB/32, 6), 256, smG>>>(x, Wq, Wk, Wv);
    filter_kernel<<<152, 512, smF>>>(f_ij, r_ij, Wf1, bf1, Wf2, bf2, outW);
    attn_out_kernel<<<512, 256, smA>>>(neighbors, pmask, outW, Wo, bo, outM);
}

// round 14
// speedup vs baseline: 1.6009x; 1.5485x over previous
#include <cuda_runtime.h>
#include <cuda_fp16.h>
#include <cstdint>
#include <math.h>

#define NAB 4096
#define NA  2048
#define NN  48
#define FF  128
#define NPAIR (NAB*NN)       // 196608
#define NTILES (NPAIR/128)   // 1536
#define RCUT 5.0f

// A-operand packed strides (bytes/row): ≡64 mod 128 -> conflict-free LDS.128
#define ST1A 320   // K=64:  4 ksteps * 64B + 64 pad
#define ST2A 576   // K=128: 8 ksteps * 64B + 64 pad
// B-operand packed strides: ≡32 mod 128 -> conflict-free LDS.64
#define ST1B 160   // K=64:  4 ksteps * 32B + 32 pad
#define ST2B 288   // K=128: 8 ksteps * 32B + 32 pad

// dynamic smem byte offsets (filter kernel)
#define SM_G   0                      // 128*320  = 40960
#define SM_H   40960                  // 128*576  = 73728
#define SM_B1  114688                 // 128*160  = 20480
#define SM_B2  135168                 // 128*288  = 36864
#define SM_TOT 172032

// Scratch (__device__ globals; no allocations allowed)
__device__ float g_Q[NAB*FF];
__device__ float g_K[NAB*FF];
__device__ float g_V[NAB*FF];

// ---------------------------------------------------------------------------
__device__ __forceinline__ float sspf(float z){
    float az = fabsf(z);
    float e = __expf(-az);
    return fmaxf(z, 0.f) + __logf(1.f + e) - 0.69314718055994531f;
}

// exact fp16 split of a pair: hi word + lo word (a = hi + lo to 2^-22)
__device__ __forceinline__ void split2h(float a, float b, uint32_t &hi, uint32_t &lo){
    __half ah = __float2half(a);
    __half bh = __float2half(b);
    __half al = __float2half(a - __half2float(ah));
    __half bl = __float2half(b - __half2float(bh));
    hi = ((uint32_t)__half_as_ushort(bh) << 16) | (uint32_t)__half_as_ushort(ah);
    lo = ((uint32_t)__half_as_ushort(bl) << 16) | (uint32_t)__half_as_ushort(al);
}
__device__ __forceinline__ uint32_t pack2h(float a, float b){
    return ((uint32_t)__half_as_ushort(__float2half(b)) << 16) |
           (uint32_t)__half_as_ushort(__float2half(a));
}

// A packed addr (pair at even k): granule 16B = {hi(k),hi(k+8),lo(k),lo(k+8)}
__device__ __forceinline__ uint32_t pkA(int row, int k, int st){
    return (uint32_t)(row*st + ((k >> 4) << 6) + (((k & 7) >> 1) << 4) + ((k & 8) >> 1));
}
// B packed addr: unit 8B = {b(k), b(k+8)}
__device__ __forceinline__ uint32_t pkB(int row, int k, int st){
    return (uint32_t)(row*st + ((k >> 4) << 5) + (((k & 7) >> 1) << 3) + ((k & 8) >> 1));
}

__device__ __forceinline__ void mma_f16(float* c, uint32_t a0, uint32_t a1, uint32_t a2, uint32_t a3,
                                        uint32_t b0, uint32_t b1){
    asm volatile(
        "mma.sync.aligned.m16n8k16.row.col.f32.f16.f16.f32 "
        "{%0,%1,%2,%3}, {%4,%5,%6,%7}, {%8,%9}, {%0,%1,%2,%3};"
        : "+f"(c[0]), "+f"(c[1]), "+f"(c[2]), "+f"(c[3])
        : "r"(a0), "r"(a1), "r"(a2), "r"(a3), "r"(b0), "r"(b1));
}

// fp16 2-pass GEMM (A split hi/lo exact, B single): warp tile 32x32
template<int KSTEPS, int STA, int STB>
__device__ __forceinline__ void gemm2p(
    const char* __restrict__ A, const char* __restrict__ Bm,
    int m0, int n0, int lane, float acc[2][4][4])
{
    const int rq = lane >> 2, q = lane & 3;
    #pragma unroll
    for (int ks = 0; ks < KSTEPS; ks++){
        const char* Ab = A + ks*64 + q*16;
        const char* Bb = Bm + ks*32 + q*8;
        uint4 a0[2], a1[2]; uint2 bb[4];
        #pragma unroll
        for (int mf = 0; mf < 2; mf++){
            a0[mf] = *(const uint4*)(Ab + (m0 + mf*16 + rq)*STA);
            a1[mf] = *(const uint4*)(Ab + (m0 + mf*16 + 8 + rq)*STA);
        }
        #pragma unroll
        for (int nf = 0; nf < 4; nf++)
            bb[nf] = *(const uint2*)(Bb + (n0 + nf*8 + rq)*STB);
        #pragma unroll
        for (int mf = 0; mf < 2; mf++)
            #pragma unroll
            for (int nf = 0; nf < 4; nf++){
                mma_f16(acc[mf][nf], a0[mf].x, a1[mf].x, a0[mf].y, a1[mf].y, bb[nf].x, bb[nf].y); // hi
                mma_f16(acc[mf][nf], a0[mf].z, a1[mf].z, a0[mf].w, a1[mf].w, bb[nf].x, bb[nf].y); // lo
            }
    }
}

// ---------------------------------------------------------------------------
// Persistent fused filter network (fp16x2 HMMA), 512 threads / 16 warps,
// cross-tile register prefetch of f_ij
// ---------------------------------------------------------------------------
__global__ void __launch_bounds__(512,1) filter_kernel(
    const float* __restrict__ f_ij, const float* __restrict__ r_ij,
    const float* __restrict__ Wf1, const float* __restrict__ bf1,
    const float* __restrict__ Wf2, const float* __restrict__ bf2,
    float* __restrict__ outW)
{
    extern __shared__ __align__(128) char dynsm[];
    __shared__ float s_cw[128], s_bf1[128], s_bf2[128];

    char* G  = dynsm + SM_G;
    char* H  = dynsm + SM_H;
    char* B1 = dynsm + SM_B1;
    char* B2 = dynsm + SM_B2;

    const int tid  = threadIdx.x;
    const int lane = tid & 31, wid = tid >> 5;
    const int m0 = (wid & 3) * 32;
    const int n0 = (wid >> 2) * 32;
    const int rq = lane >> 2, q = lane & 3;

    // ---- weight prep (once per persistent block): transpose + pack fp16 ----
    for (int i = tid; i < 128*32; i += 512){
        int n = i >> 5, p = i & 31, k = p*2;
        float v0 = (k   < 50) ? Wf1[k*FF + n]     : 0.f;
        float v1 = (k+1 < 50) ? Wf1[(k+1)*FF + n] : 0.f;
        *(uint32_t*)(B1 + pkB(n, k, ST1B)) = pack2h(v0, v1);
    }
    for (int i = tid; i < 128*64; i += 512){
        int n = i >> 6, p = i & 63, k = p*2;
        *(uint32_t*)(B2 + pkB(n, k, ST2B)) = pack2h(Wf2[k*FF + n], Wf2[(k+1)*FF + n]);
    }
    if (tid < 128){ s_bf1[tid] = bf1[tid]; s_bf2[tid] = bf2[tid]; }

    // per-thread static pieces of the G address
    const int grow = tid >> 5;          // row handled at u-stride: row = grow + u*16
    const int gp   = tid & 31;          // packed pair index
    const int gk   = gp * 2;

    // ---- prologue: load tile t0 into G ----
    {
        const int tb0 = blockIdx.x * 128;
        #pragma unroll
        for (int u = 0; u < 8; u++){
            int row = grow + u*16;
            float2 v = (gp < 25) ? *(const float2*)(f_ij + (size_t)(tb0+row)*50 + gk)
                                 : make_float2(0.5f, 0.5f);
            uint32_t hi, lo; split2h(2.f*v.x - 1.f, 2.f*v.y - 1.f, hi, lo);
            uint32_t a = pkA(row, gk, ST1A);
            *(uint32_t*)(G + a)     = hi;
            *(uint32_t*)(G + a + 8) = lo;
        }
        if (tid < 128){
            float r = r_ij[tb0 + tid];
            s_cw[tid] = (r < RCUT) ? 0.5f*(__cosf(0.62831853071795865f*r) + 1.f) : 0.f;
        }
    }

    for (int t = blockIdx.x; t < NTILES; t += gridDim.x){
        const int tb = t * 128;
        __syncthreads();   // S1: G + s_cw(t) visible

        // cutoff weights for this warp's rows -> regs
        float rcw0 = s_cw[m0 + rq],      rcw1 = s_cw[m0 + rq + 8];
        float rcw2 = s_cw[m0 + 16 + rq], rcw3 = s_cw[m0 + 16 + rq + 8];

        // ---- GEMM1: D1 = G @ Wf1 ----
        float acc[2][4][4];
        #pragma unroll
        for (int mf=0;mf<2;mf++)
            #pragma unroll
            for (int nf=0;nf<4;nf++)
                #pragma unroll
                for (int u=0;u<4;u++) acc[mf][nf][u] = 0.f;
        gemm2p<4, ST1A, ST1B>(G, B1, m0, n0, lane, acc);

        // ---- epilogue 1: H = ssp(D1 + bf1) -> fp16-split packed into H ----
        #pragma unroll
        for (int mf = 0; mf < 2; mf++){
            const int r = m0 + mf*16 + rq;
            #pragma unroll
            for (int nfp = 0; nfp < 4; nfp += 2){
                int ccA = n0 + nfp*8 + 2*q;
                int ccB = ccA + 8;
                float b0 = s_bf1[ccA], b1 = s_bf1[ccA+1];
                float b2 = s_bf1[ccB], b3 = s_bf1[ccB+1];
                uint32_t h0,l0,h1,l1;
                uint32_t ad = (uint32_t)(r*ST2A + ((n0 + nfp*8) >> 4)*64 + q*16);
                split2h(sspf(acc[mf][nfp][0]+b0),   sspf(acc[mf][nfp][1]+b1),   h0, l0);
                split2h(sspf(acc[mf][nfp+1][0]+b2), sspf(acc[mf][nfp+1][1]+b3), h1, l1);
                *(uint4*)(H + ad) = make_uint4(h0, h1, l0, l1);
                split2h(sspf(acc[mf][nfp][2]+b0),   sspf(acc[mf][nfp][3]+b1),   h0, l0);
                split2h(sspf(acc[mf][nfp+1][2]+b2), sspf(acc[mf][nfp+1][3]+b3), h1, l1);
                *(uint4*)(H + ad + 8*ST2A) = make_uint4(h0, h1, l0, l1);
            }
        }
        __syncthreads();   // S2: G dead, H ready

        // ---- prefetch next tile's f_ij into registers (hidden by GEMM2) ----
        const int tn = t + gridDim.x;
        const bool hasn = (tn < NTILES);
        float2 pf[8];
        float rnext = 0.f;
        if (hasn){
            const int tbn = tn * 128;
            #pragma unroll
            for (int u = 0; u < 8; u++){
                int row = grow + u*16;
                pf[u] = (gp < 25) ? *(const float2*)(f_ij + (size_t)(tbn+row)*50 + gk)
                                  : make_float2(0.5f, 0.5f);
            }
            if (tid < 128) rnext = r_ij[tbn + tid];
        }

        // ---- GEMM2: D2 = H @ Wf2 ----
        #pragma unroll
        for (int mf=0;mf<2;mf++)
            #pragma unroll
            for (int nf=0;nf<4;nf++)
                #pragma unroll
                for (int u=0;u<4;u++) acc[mf][nf][u] = 0.f;
        gemm2p<8, ST2A, ST2B>(H, B2, m0, n0, lane, acc);

        // ---- epilogue 2: W = (D2 + bf2) * cutoff, direct global store ----
        #pragma unroll
        for (int mf = 0; mf < 2; mf++){
            int rr = m0 + mf*16 + rq;
            float cw0 = mf ? rcw2 : rcw0;
            float cw1 = mf ? rcw3 : rcw1;
            #pragma unroll
            for (int nf = 0; nf < 4; nf++){
                int cc = n0 + nf*8 + 2*q;
                float b0 = s_bf2[cc], b1 = s_bf2[cc+1];
                float2 o0, o1;
                o0.x = (acc[mf][nf][0] + b0) * cw0;
                o0.y = (acc[mf][nf][1] + b1) * cw0;
                o1.x = (acc[mf][nf][2] + b0) * cw1;
                o1.y = (acc[mf][nf][3] + b1) * cw1;
                *(float2*)&outW[((size_t)(tb + rr))*FF + cc]     = o0;
                *(float2*)&outW[((size_t)(tb + rr + 8))*FF + cc] = o1;
            }
        }

        // ---- commit prefetched tile into G (G free since S2) ----
        if (hasn){
            #pragma unroll
            for (int u = 0; u < 8; u++){
                int row = grow + u*16;
                uint32_t hi, lo; split2h(2.f*pf[u].x - 1.f, 2.f*pf[u].y - 1.f, hi, lo);
                uint32_t a = pkA(row, gk, ST1A);
                *(uint32_t*)(G + a)     = hi;
                *(uint32_t*)(G + a + 8) = lo;
            }
            if (tid < 128)
                s_cw[tid] = (rnext < RCUT) ? 0.5f*(__cosf(0.62831853071795865f*rnext) + 1.f) : 0.f;
        }
        // next-iteration S1 publishes G/s_cw
    }
}

// ---------------------------------------------------------------------------
// QKV: x @ {Wq,Wk,Wv}, 64-row x 64-col blocks (gridDim.y = 6)
// ---------------------------------------------------------------------------
__global__ void __launch_bounds__(256) qkv_kernel(
    const float* __restrict__ x,
    const float* __restrict__ Wq, const float* __restrict__ Wk, const float* __restrict__ Wv)
{
    extern __shared__ char dynsm[];
    float* sW = (float*)dynsm;          // [128][64] = 32 KB
    float* sX = sW + FF*64;             // [64][128] = 32 KB
    const int mat  = blockIdx.y >> 1;
    const int half = blockIdx.y & 1;
    const float* Wsrc = (mat == 0) ? Wq : (mat == 1 ? Wk : Wv);
    float* outp = (mat == 0) ? g_Q : (mat == 1 ? g_K : g_V);
    const int tid = threadIdx.x;
    const int row0 = blockIdx.x * 64;

    for (int i = tid; i < FF*32; i += 256){
        int k = i >> 5, c2 = (i & 31)*2;
        *(float2*)&sW[k*64 + c2] = *(const float2*)&Wsrc[k*FF + half*64 + c2];
    }
    for (int i = tid*4; i < 64*FF; i += 1024)
        *(float4*)&sX[i] = *(const float4*)&x[(size_t)row0*FF + i];
    __syncthreads();

    const int lane = tid & 31, wd = tid >> 5;
    const int c0 = lane * 2;
    float acc[8][2];
    #pragma unroll
    for (int m=0;m<8;m++){ acc[m][0]=0.f; acc[m][1]=0.f; }

    for (int k = 0; k < FF; k += 4){
        float2 bf[4];
        #pragma unroll
        for (int kk=0;kk<4;kk++) bf[kk] = *(float2*)&sW[(k+kk)*64 + c0];
        #pragma unroll
        for (int m=0;m<8;m++){
            float4 av = *(float4*)&sX[(wd*8+m)*FF + k];
            acc[m][0] = fmaf(av.x, bf[0].x, acc[m][0]); acc[m][1] = fmaf(av.x, bf[0].y, acc[m][1]);
            acc[m][0] = fmaf(av.y, bf[1].x, acc[m][0]); acc[m][1] = fmaf(av.y, bf[1].y, acc[m][1]);
            acc[m][0] = fmaf(av.z, bf[2].x, acc[m][0]); acc[m][1] = fmaf(av.z, bf[2].y, acc[m][1]);
            acc[m][0] = fmaf(av.w, bf[3].x, acc[m][0]); acc[m][1] = fmaf(av.w, bf[3].y, acc[m][1]);
        }
    }
    #pragma unroll
    for (int m=0;m<8;m++){
        int r = row0 + wd*8 + m;
        *(float2*)&outp[(size_t)r*FF + half*64 + c0] = make_float2(acc[m][0], acc[m][1]);
    }
}

// ---------------------------------------------------------------------------
// Attention aggregation + fused output projection (R7 structure, untouched)
// ---------------------------------------------------------------------------
__global__ void __launch_bounds__(128) attn_out_kernel(
    const int* __restrict__ neighbors, const int* __restrict__ pmask,
    const float* __restrict__ W,
    const float* __restrict__ Wo, const float* __restrict__ bo,
    float* __restrict__ outM)
{
    __shared__ float s_q[128];
    __shared__ float s_sc[64];
    __shared__ float s_at[64];
    __shared__ float s_m[128];
    __shared__ int s_nb[48];
    __shared__ int s_mk[48];
    const int atom = blockIdx.x;
    const int tid = threadIdx.x, lane = tid & 31, wd = tid >> 5;

    s_q[tid] = g_Q[(size_t)atom*FF + tid];
    if (tid < NN){
        s_nb[tid] = neighbors[atom*NN + tid] + (atom >> 11)*NA;
        s_mk[tid] = pmask[atom*NN + tid];
    }
    __syncthreads();

    for (int j = wd; j < 49; j += 4){
        int row = j ? s_nb[j-1] : atom;
        float4 kv = *(const float4*)&g_K[(size_t)row*FF + lane*4];
        float4 qv = *(const float4*)&s_q[lane*4];
        float d = kv.x*qv.x + kv.y*qv.y + kv.z*qv.z + kv.w*qv.w;
        #pragma unroll
        for (int o=16;o;o>>=1) d += __shfl_xor_sync(0xffffffffu, d, o);
        if (lane == 0){
            float s = d * 0.08838834764831845f;  // 1/sqrt(128)
            if (j > 0 && s_mk[j-1] == 0) s = -1e9f;
            s_sc[j] = s;
        }
    }
    __syncthreads();

    if (wd == 0){
        float v0 = (lane      < 49) ? s_sc[lane]      : -3.4e38f;
        float v1 = (lane + 32 < 49) ? s_sc[lane + 32] : -3.4e38f;
        float mx = fmaxf(v0, v1);
        #pragma unroll
        for (int o=16;o;o>>=1) mx = fmaxf(mx, __shfl_xor_sync(0xffffffffu, mx, o));
        float e0 = (lane      < 49) ? __expf(v0 - mx) : 0.f;
        float e1 = (lane + 32 < 49) ? __expf(v1 - mx) : 0.f;
        float s = e0 + e1;
        #pragma unroll
        for (int o=16;o;o>>=1) s += __shfl_xor_sync(0xffffffffu, s, o);
        float inv = 1.f / s;
        if (lane      < 49) s_at[lane]      = e0 * inv;
        if (lane + 32 < 49) s_at[lane + 32] = e1 * inv;
    }
    __syncthreads();

    float acc = s_at[0] * g_V[(size_t)atom*FF + tid];
    const float* wrow = W + (size_t)atom*NN*FF + tid;
    #pragma unroll 4
    for (int j = 0; j < NN; j++)
        acc += s_at[j+1] * g_V[(size_t)s_nb[j]*FF + tid] * wrow[(size_t)j*FF];
    s_m[tid] = acc;
    __syncthreads();

    // fused: out = ssp(m @ Wo + bo); lanes read Wo rows coalesced (L1/L2-resident)
    float o0 = 0.f, o1 = 0.f;
    #pragma unroll 8
    for (int k = 0; k < FF; k += 2){
        o0 = fmaf(s_m[k],   Wo[(size_t)k*FF + tid],     o0);
        o1 = fmaf(s_m[k+1], Wo[(size_t)(k+1)*FF + tid], o1);
    }
    outM[(size_t)atom*FF + tid] = sspf(o0 + o1 + bo[tid]);
}

// ---------------------------------------------------------------------------
extern "C" void kernel_launch(void* const* d_in, const int* in_sizes, int n_in,
                              void* d_out, int out_size)
{
    // order: e,x,t,r_ij,neighbors,pairwise_mask,f_ij,Wf1,bf1,Wf2,bf2,Wq,Wk,Wv,Wo,bo
    const float* x         = (const float*)d_in[1];
    const float* r_ij      = (const float*)d_in[3];
    const int*   neighbors = (const int*)  d_in[4];
    const int*   pmask     = (const int*)  d_in[5];
    const float* f_ij      = (const float*)d_in[6];
    const float* Wf1       = (const float*)d_in[7];
    const float* bf1       = (const float*)d_in[8];
    const float* Wf2       = (const float*)d_in[9];
    const float* bf2       = (const float*)d_in[10];
    const float* Wq        = (const float*)d_in[11];
    const float* Wk        = (const float*)d_in[12];
    const float* Wv        = (const float*)d_in[13];
    const float* Wo        = (const float*)d_in[14];
    const float* bo        = (const float*)d_in[15];

    float* out  = (float*)d_out;
    float* outM = out;                        // m: [B,Na,F]
    float* outW = out + (size_t)NAB * FF;     // W: [B,Na,Nn,F]

    size_t smG = (size_t)(FF*64 + 64*FF) * sizeof(float);   // 64 KB
    size_t smF = SM_TOT;                                    // 168 KB

    cudaFuncSetAttribute(qkv_kernel,    cudaFuncAttributeMaxDynamicSharedMemorySize, (int)smG);
    cudaFuncSetAttribute(filter_kernel, cudaFuncAttributeMaxDynamicSharedMemorySize, (int)smF);

    qkv_kernel<<<dim3(NAB/64, 6), 256, smG>>>(x, Wq, Wk, Wv);
    filter_kernel<<<152, 512, smF>>>(f_ij, r_ij, Wf1, bf1, Wf2, bf2, outW);
    attn_out_kernel<<<NAB, 128>>>(neighbors, pmask, outW, Wo, bo, outM);
}

// round 15
// speedup vs baseline: 1.8968x; 1.1848x over previous
#include <cuda_runtime.h>
#include <cuda_fp16.h>
#include <cstdint>
#include <math.h>

#define NAB 4096
#define NA  2048
#define NN  48
#define FF  128
#define NPAIR (NAB*NN)       // 196608
#define NTILES (NPAIR/128)   // 1536
#define RCUT 5.0f

// packed pair-granule strides (bytes/row): ≡32 mod 128 -> conflict-free LDS.64
#define ST1 160   // K=64:  4 ksteps * 32B + 32 pad
#define ST2 288   // K=128: 8 ksteps * 32B + 32 pad

// dynamic smem byte offsets (filter kernel)
#define SM_G   0                      // 128*160 = 20480
#define SM_H   20480                  // 128*288 = 36864
#define SM_B1  57344                  // 128*160 = 20480
#define SM_B2  77824                  // 128*288 = 36864
#define SM_TOT 114688

// Scratch (__device__ globals; no allocations allowed)
__device__ float g_Q[NAB*FF];
__device__ float g_K[NAB*FF];
__device__ float g_V[NAB*FF];

// ---------------------------------------------------------------------------
__device__ __forceinline__ float sspf(float z){
    float az = fabsf(z);
    float e = __expf(-az);
    return fmaxf(z, 0.f) + __logf(1.f + e) - 0.69314718055994531f;
}

__device__ __forceinline__ uint32_t pack2h(float a, float b){
    return ((uint32_t)__half_as_ushort(__float2half(b)) << 16) |
           (uint32_t)__half_as_ushort(__float2half(a));
}

// packed pair addr: 8B granule = {pair(k,k+1), pair(k+8,k+9)} per row
__device__ __forceinline__ uint32_t pkP(int row, int k, int st){
    return (uint32_t)(row*st + ((k >> 4) << 5) + (((k & 7) >> 1) << 3) + ((k & 8) >> 1));
}

__device__ __forceinline__ void mma_f16(float* c, uint32_t a0, uint32_t a1, uint32_t a2, uint32_t a3,
                                        uint32_t b0, uint32_t b1){
    asm volatile(
        "mma.sync.aligned.m16n8k16.row.col.f32.f16.f16.f32 "
        "{%0,%1,%2,%3}, {%4,%5,%6,%7}, {%8,%9}, {%0,%1,%2,%3};"
        : "+f"(c[0]), "+f"(c[1]), "+f"(c[2]), "+f"(c[3])
        : "r"(a0), "r"(a1), "r"(a2), "r"(a3), "r"(b0), "r"(b1));
}

// fp16 single-pass GEMM (A and B plain fp16): warp tile 32x32
template<int KSTEPS, int ST>
__device__ __forceinline__ void gemm1p(
    const char* __restrict__ A, const char* __restrict__ Bm,
    int m0, int n0, int lane, float acc[2][4][4])
{
    const int rq = lane >> 2, q = lane & 3;
    #pragma unroll
    for (int ks = 0; ks < KSTEPS; ks++){
        const char* Ab = A + ks*32 + q*8;
        const char* Bb = Bm + ks*32 + q*8;
        uint2 a0[2], a1[2], bb[4];
        #pragma unroll
        for (int mf = 0; mf < 2; mf++){
            a0[mf] = *(const uint2*)(Ab + (m0 + mf*16 + rq)*ST);
            a1[mf] = *(const uint2*)(Ab + (m0 + mf*16 + 8 + rq)*ST);
        }
        #pragma unroll
        for (int nf = 0; nf < 4; nf++)
            bb[nf] = *(const uint2*)(Bb + (n0 + nf*8 + rq)*ST);
        #pragma unroll
        for (int mf = 0; mf < 2; mf++)
            #pragma unroll
            for (int nf = 0; nf < 4; nf++)
                mma_f16(acc[mf][nf], a0[mf].x, a1[mf].x, a0[mf].y, a1[mf].y, bb[nf].x, bb[nf].y);
    }
}

// ---------------------------------------------------------------------------
// Persistent fused filter network (pure fp16 HMMA), 512 threads / 16 warps,
// cross-tile register prefetch of f_ij
// ---------------------------------------------------------------------------
__global__ void __launch_bounds__(512,1) filter_kernel(
    const float* __restrict__ f_ij, const float* __restrict__ r_ij,
    const float* __restrict__ Wf1, const float* __restrict__ bf1,
    const float* __restrict__ Wf2, const float* __restrict__ bf2,
    float* __restrict__ outW)
{
    extern __shared__ __align__(128) char dynsm[];
    __shared__ float s_cw[128], s_bf1[128], s_bf2[128];

    char* G  = dynsm + SM_G;
    char* H  = dynsm + SM_H;
    char* B1 = dynsm + SM_B1;
    char* B2 = dynsm + SM_B2;

    const int tid  = threadIdx.x;
    const int lane = tid & 31, wid = tid >> 5;
    const int m0 = (wid & 3) * 32;
    const int n0 = (wid >> 2) * 32;
    const int rq = lane >> 2, q = lane & 3;

    // ---- weight prep (once per persistent block): transpose + pack fp16 ----
    for (int i = tid; i < 128*32; i += 512){
        int n = i >> 5, p = i & 31, k = p*2;
        float v0 = (k   < 50) ? Wf1[k*FF + n]     : 0.f;
        float v1 = (k+1 < 50) ? Wf1[(k+1)*FF + n] : 0.f;
        *(uint32_t*)(B1 + pkP(n, k, ST1)) = pack2h(v0, v1);
    }
    for (int i = tid; i < 128*64; i += 512){
        int n = i >> 6, p = i & 63, k = p*2;
        *(uint32_t*)(B2 + pkP(n, k, ST2)) = pack2h(Wf2[k*FF + n], Wf2[(k+1)*FF + n]);
    }
    if (tid < 128){ s_bf1[tid] = bf1[tid]; s_bf2[tid] = bf2[tid]; }

    // per-thread static pieces of the G address
    const int grow = tid >> 5;          // row handled at u-stride: row = grow + u*16
    const int gp   = tid & 31;          // packed pair index
    const int gk   = gp * 2;

    // ---- prologue: load tile t0 into G ----
    {
        const int tb0 = blockIdx.x * 128;
        #pragma unroll
        for (int u = 0; u < 8; u++){
            int row = grow + u*16;
            float2 v = (gp < 25) ? *(const float2*)(f_ij + (size_t)(tb0+row)*50 + gk)
                                 : make_float2(0.5f, 0.5f);
            *(uint32_t*)(G + pkP(row, gk, ST1)) = pack2h(2.f*v.x - 1.f, 2.f*v.y - 1.f);
        }
        if (tid < 128){
            float r = r_ij[tb0 + tid];
            s_cw[tid] = (r < RCUT) ? 0.5f*(__cosf(0.62831853071795865f*r) + 1.f) : 0.f;
        }
    }

    for (int t = blockIdx.x; t < NTILES; t += gridDim.x){
        const int tb = t * 128;
        __syncthreads();   // S1: G + s_cw(t) visible

        // cutoff weights for this warp's rows -> regs
        float rcw0 = s_cw[m0 + rq],      rcw1 = s_cw[m0 + rq + 8];
        float rcw2 = s_cw[m0 + 16 + rq], rcw3 = s_cw[m0 + 16 + rq + 8];

        // ---- GEMM1: D1 = G @ Wf1 ----
        float acc[2][4][4];
        #pragma unroll
        for (int mf=0;mf<2;mf++)
            #pragma unroll
            for (int nf=0;nf<4;nf++)
                #pragma unroll
                for (int u=0;u<4;u++) acc[mf][nf][u] = 0.f;
        gemm1p<4, ST1>(G, B1, m0, n0, lane, acc);

        // ---- epilogue 1: H = ssp(D1 + bf1) -> fp16 packed into H ----
        #pragma unroll
        for (int mf = 0; mf < 2; mf++){
            const int r = m0 + mf*16 + rq;
            #pragma unroll
            for (int nfp = 0; nfp < 4; nfp += 2){
                int ccA = n0 + nfp*8 + 2*q;
                int ccB = ccA + 8;
                float b0 = s_bf1[ccA], b1 = s_bf1[ccA+1];
                float b2 = s_bf1[ccB], b3 = s_bf1[ccB+1];
                uint32_t ad = pkP(r, ccA, ST2);
                uint2 w0, w1;
                w0.x = pack2h(sspf(acc[mf][nfp][0]+b0),   sspf(acc[mf][nfp][1]+b1));
                w0.y = pack2h(sspf(acc[mf][nfp+1][0]+b2), sspf(acc[mf][nfp+1][1]+b3));
                *(uint2*)(H + ad) = w0;
                w1.x = pack2h(sspf(acc[mf][nfp][2]+b0),   sspf(acc[mf][nfp][3]+b1));
                w1.y = pack2h(sspf(acc[mf][nfp+1][2]+b2), sspf(acc[mf][nfp+1][3]+b3));
                *(uint2*)(H + ad + 8*ST2) = w1;
            }
        }
        __syncthreads();   // S2: G dead, H ready

        // ---- prefetch next tile's f_ij into registers (hidden by GEMM2) ----
        const int tn = t + gridDim.x;
        const bool hasn = (tn < NTILES);
        float2 pf[8];
        float rnext = 0.f;
        if (hasn){
            const int tbn = tn * 128;
            #pragma unroll
            for (int u = 0; u < 8; u++){
                int row = grow + u*16;
                pf[u] = (gp < 25) ? *(const float2*)(f_ij + (size_t)(tbn+row)*50 + gk)
                                  : make_float2(0.5f, 0.5f);
            }
            if (tid < 128) rnext = r_ij[tbn + tid];
        }

        // ---- GEMM2: D2 = H @ Wf2 ----
        #pragma unroll
        for (int mf=0;mf<2;mf++)
            #pragma unroll
            for (int nf=0;nf<4;nf++)
                #pragma unroll
                for (int u=0;u<4;u++) acc[mf][nf][u] = 0.f;
        gemm1p<8, ST2>(H, B2, m0, n0, lane, acc);

        // ---- epilogue 2: W = (D2 + bf2) * cutoff, direct global store ----
        #pragma unroll
        for (int mf = 0; mf < 2; mf++){
            int rr = m0 + mf*16 + rq;
            float cw0 = mf ? rcw2 : rcw0;
            float cw1 = mf ? rcw3 : rcw1;
            #pragma unroll
            for (int nf = 0; nf < 4; nf++){
                int cc = n0 + nf*8 + 2*q;
                float b0 = s_bf2[cc], b1 = s_bf2[cc+1];
                float2 o0, o1;
                o0.x = (acc[mf][nf][0] + b0) * cw0;
                o0.y = (acc[mf][nf][1] + b1) * cw0;
                o1.x = (acc[mf][nf][2] + b0) * cw1;
                o1.y = (acc[mf][nf][3] + b1) * cw1;
                *(float2*)&outW[((size_t)(tb + rr))*FF + cc]     = o0;
                *(float2*)&outW[((size_t)(tb + rr + 8))*FF + cc] = o1;
            }
        }

        // ---- commit prefetched tile into G (G free since S2) ----
        if (hasn){
            #pragma unroll
            for (int u = 0; u < 8; u++){
                int row = grow + u*16;
                *(uint32_t*)(G + pkP(row, gk, ST1)) = pack2h(2.f*pf[u].x - 1.f, 2.f*pf[u].y - 1.f);
            }
            if (tid < 128)
                s_cw[tid] = (rnext < RCUT) ? 0.5f*(__cosf(0.62831853071795865f*rnext) + 1.f) : 0.f;
        }
        // next-iteration S1 publishes G/s_cw
    }
}

// ---------------------------------------------------------------------------
// QKV: x @ {Wq,Wk,Wv}, 64-row x 64-col blocks (gridDim.y = 6)
// ---------------------------------------------------------------------------
__global__ void __launch_bounds__(256) qkv_kernel(
    const float* __restrict__ x,
    const float* __restrict__ Wq, const float* __restrict__ Wk, const float* __restrict__ Wv)
{
    extern __shared__ char dynsm[];
    float* sW = (float*)dynsm;          // [128][64] = 32 KB
    float* sX = sW + FF*64;             // [64][128] = 32 KB
    const int mat  = blockIdx.y >> 1;
    const int half = blockIdx.y & 1;
    const float* Wsrc = (mat == 0) ? Wq : (mat == 1 ? Wk : Wv);
    float* outp = (mat == 0) ? g_Q : (mat == 1 ? g_K : g_V);
    const int tid = threadIdx.x;
    const int row0 = blockIdx.x * 64;

    for (int i = tid; i < FF*32; i += 256){
        int k = i >> 5, c2 = (i & 31)*2;
        *(float2*)&sW[k*64 + c2] = *(const float2*)&Wsrc[k*FF + half*64 + c2];
    }
    for (int i = tid*4; i < 64*FF; i += 1024)
        *(float4*)&sX[i] = *(const float4*)&x[(size_t)row0*FF + i];
    __syncthreads();

    const int lane = tid & 31, wd = tid >> 5;
    const int c0 = lane * 2;
    float acc[8][2];
    #pragma unroll
    for (int m=0;m<8;m++){ acc[m][0]=0.f; acc[m][1]=0.f; }

    for (int k = 0; k < FF; k += 4){
        float2 bf[4];
        #pragma unroll
        for (int kk=0;kk<4;kk++) bf[kk] = *(float2*)&sW[(k+kk)*64 + c0];
        #pragma unroll
        for (int m=0;m<8;m++){
            float4 av = *(float4*)&sX[(wd*8+m)*FF + k];
            acc[m][0] = fmaf(av.x, bf[0].x, acc[m][0]); acc[m][1] = fmaf(av.x, bf[0].y, acc[m][1]);
            acc[m][0] = fmaf(av.y, bf[1].x, acc[m][0]); acc[m][1] = fmaf(av.y, bf[1].y, acc[m][1]);
            acc[m][0] = fmaf(av.z, bf[2].x, acc[m][0]); acc[m][1] = fmaf(av.z, bf[2].y, acc[m][1]);
            acc[m][0] = fmaf(av.w, bf[3].x, acc[m][0]); acc[m][1] = fmaf(av.w, bf[3].y, acc[m][1]);
        }
    }
    #pragma unroll
    for (int m=0;m<8;m++){
        int r = row0 + wd*8 + m;
        *(float2*)&outp[(size_t)r*FF + half*64 + c0] = make_float2(acc[m][0], acc[m][1]);
    }
}

// ---------------------------------------------------------------------------
// Attention aggregation + fused output projection (R7 structure, untouched)
// ---------------------------------------------------------------------------
__global__ void __launch_bounds__(128) attn_out_kernel(
    const int* __restrict__ neighbors, const int* __restrict__ pmask,
    const float* __restrict__ W,
    const float* __restrict__ Wo, const float* __restrict__ bo,
    float* __restrict__ outM)
{
    __shared__ float s_q[128];
    __shared__ float s_sc[64];
    __shared__ float s_at[64];
    __shared__ float s_m[128];
    __shared__ int s_nb[48];
    __shared__ int s_mk[48];
    const int atom = blockIdx.x;
    const int tid = threadIdx.x, lane = tid & 31, wd = tid >> 5;

    s_q[tid] = g_Q[(size_t)atom*FF + tid];
    if (tid < NN){
        s_nb[tid] = neighbors[atom*NN + tid] + (atom >> 11)*NA;
        s_mk[tid] = pmask[atom*NN + tid];
    }
    __syncthreads();

    for (int j = wd; j < 49; j += 4){
        int row = j ? s_nb[j-1] : atom;
        float4 kv = *(const float4*)&g_K[(size_t)row*FF + lane*4];
        float4 qv = *(const float4*)&s_q[lane*4];
        float d = kv.x*qv.x + kv.y*qv.y + kv.z*qv.z + kv.w*qv.w;
        #pragma unroll
        for (int o=16;o;o>>=1) d += __shfl_xor_sync(0xffffffffu, d, o);
        if (lane == 0){
            float s = d * 0.08838834764831845f;  // 1/sqrt(128)
            if (j > 0 && s_mk[j-1] == 0) s = -1e9f;
            s_sc[j] = s;
        }
    }
    __syncthreads();

    if (wd == 0){
        float v0 = (lane      < 49) ? s_sc[lane]      : -3.4e38f;
        float v1 = (lane + 32 < 49) ? s_sc[lane + 32] : -3.4e38f;
        float mx = fmaxf(v0, v1);
        #pragma unroll
        for (int o=16;o;o>>=1) mx = fmaxf(mx, __shfl_xor_sync(0xffffffffu, mx, o));
        float e0 = (lane      < 49) ? __expf(v0 - mx) : 0.f;
        float e1 = (lane + 32 < 49) ? __expf(v1 - mx) : 0.f;
        float s = e0 + e1;
        #pragma unroll
        for (int o=16;o;o>>=1) s += __shfl_xor_sync(0xffffffffu, s, o);
        float inv = 1.f / s;
        if (lane      < 49) s_at[lane]      = e0 * inv;
        if (lane + 32 < 49) s_at[lane + 32] = e1 * inv;
    }
    __syncthreads();

    float acc = s_at[0] * g_V[(size_t)atom*FF + tid];
    const float* wrow = W + (size_t)atom*NN*FF + tid;
    #pragma unroll 4
    for (int j = 0; j < NN; j++)
        acc += s_at[j+1] * g_V[(size_t)s_nb[j]*FF + tid] * wrow[(size_t)j*FF];
    s_m[tid] = acc;
    __syncthreads();

    // fused: out = ssp(m @ Wo + bo); lanes read Wo rows coalesced (L1/L2-resident)
    float o0 = 0.f, o1 = 0.f;
    #pragma unroll 8
    for (int k = 0; k < FF; k += 2){
        o0 = fmaf(s_m[k],   Wo[(size_t)k*FF + tid],     o0);
        o1 = fmaf(s_m[k+1], Wo[(size_t)(k+1)*FF + tid], o1);
    }
    outM[(size_t)atom*FF + tid] = sspf(o0 + o1 + bo[tid]);
}

// ---------------------------------------------------------------------------
extern "C" void kernel_launch(void* const* d_in, const int* in_sizes, int n_in,
                              void* d_out, int out_size)
{
    // order: e,x,t,r_ij,neighbors,pairwise_mask,f_ij,Wf1,bf1,Wf2,bf2,Wq,Wk,Wv,Wo,bo
    const float* x         = (const float*)d_in[1];
    const float* r_ij      = (const float*)d_in[3];
    const int*   neighbors = (const int*)  d_in[4];
    const int*   pmask     = (const int*)  d_in[5];
    const float* f_ij      = (const float*)d_in[6];
    const float* Wf1       = (const float*)d_in[7];
    const float* bf1       = (const float*)d_in[8];
    const float* Wf2       = (const float*)d_in[9];
    const float* bf2       = (const float*)d_in[10];
    const float* Wq        = (const float*)d_in[11];
    const float* Wk        = (const float*)d_in[12];
    const float* Wv        = (const float*)d_in[13];
    const float* Wo        = (const float*)d_in[14];
    const float* bo        = (const float*)d_in[15];

    float* out  = (float*)d_out;
    float* outM = out;                        // m: [B,Na,F]
    float* outW = out + (size_t)NAB * FF;     // W: [B,Na,Nn,F]

    size_t smG = (size_t)(FF*64 + 64*FF) * sizeof(float);   // 64 KB
    size_t smF = SM_TOT;                                    // 112 KB

    cudaFuncSetAttribute(qkv_kernel,    cudaFuncAttributeMaxDynamicSharedMemorySize, (int)smG);
    cudaFuncSetAttribute(filter_kernel, cudaFuncAttributeMaxDynamicSharedMemorySize, (int)smF);

    qkv_kernel<<<dim3(NAB/64, 6), 256, smG>>>(x, Wq, Wk, Wv);
    filter_kernel<<<152, 512, smF>>>(f_ij, r_ij, Wf1, bf1, Wf2, bf2, outW);
    attn_out_kernel<<<NAB, 128>>>(neighbors, pmask, outW, Wo, bo, outM);
}